// round 2
// baseline (speedup 1.0000x reference)
#include <cuda_runtime.h>
#include <math.h>

// SlatewiseGRU: B=128, S=64, K=10, D=256.
// Key simplification: input second half is zeros => threshold mask is dead,
// input-side GEMM (GI) is recurrence-free and hoisted.

static __device__ __forceinline__ unsigned long long pack2(float x, float y) {
    unsigned long long r;
    asm("mov.b64 %0, {%1, %2};" : "=l"(r) : "f"(x), "f"(y));
    return r;
}
static __device__ __forceinline__ unsigned long long fma2(unsigned long long a,
                                                          unsigned long long b,
                                                          unsigned long long c) {
    unsigned long long d;
    asm("fma.rn.f32x2 %0, %1, %2, %3;" : "=l"(d) : "l"(a), "l"(b), "l"(c));
    return d;
}
static __device__ __forceinline__ float2 unpack2(unsigned long long v) {
    float lo, hi;
    asm("mov.b64 {%0, %1}, %2;" : "=f"(lo), "=f"(hi) : "l"(v));
    return make_float2(lo, hi);
}

// Scratch (device globals: allocation-free per harness rules)
__device__ float g_GI[62914560];   // [N*K=81920][768]  precomputed input gates (+biases)
__device__ float g_WihT[196608];   // [256][768]  = W_ih[:, :256]^T
__device__ float g_WhhT[196608];   // [256][768]  = W_hh^T

// ---------------------------------------------------------------------------
// Transpose weights into k-major layout for coalesced GEMM B-tiles.
__global__ void prep_kernel(const float* __restrict__ W_ih,
                            const float* __restrict__ W_hh) {
    int t = blockIdx.x * 256 + threadIdx.x;
    if (t >= 768 * 256) return;
    int j = t >> 8;   // 0..767 (output gate-dim)
    int k = t & 255;  // 0..255 (inner dim)
    g_WihT[k * 768 + j] = W_ih[j * 512 + k];  // only first 256 cols of W_ih matter
    g_WhhT[k * 768 + j] = W_hh[j * 256 + k];
}

// ---------------------------------------------------------------------------
// GI[r, j] = sum_k item[r,k] * W_ih[j,k] + b_ih[j] + (j<512 ? b_hh[j] : 0)
// r over 81920 rows (= n*10+k, matching item_embs memory layout directly).
// BM=128, BN=128, BK=16, 256 threads, per-thread 8x8 via f32x2 pairs.
// A tile stored pre-duplicated ({a,a} packed) so the broadcast operand needs no
// per-FMA packing.
__global__ void __launch_bounds__(256) gi_gemm(const float* __restrict__ A,
                                               const float* __restrict__ b_ih,
                                               const float* __restrict__ b_hh) {
    __shared__ unsigned long long As2[128 * 16];  // [m][k], dup-packed (16KB)
    __shared__ float Bs[16 * 128];                // [k][j]             (8KB)
    const int tid = threadIdx.x;
    const int tx = tid & 15, ty = tid >> 4;
    const int r0 = blockIdx.x * 128;
    const int j0 = blockIdx.y * 128;

    unsigned long long acc[8][4];
#pragma unroll
    for (int i = 0; i < 8; i++)
#pragma unroll
        for (int p = 0; p < 4; p++) acc[i][p] = 0ull;

    for (int k0 = 0; k0 < 256; k0 += 16) {
#pragma unroll
        for (int it = 0; it < 2; it++) {
            int f = tid + it * 256;          // 512 float4 loads of A tile
            int m = f >> 2, kk4 = f & 3;
            float4 v = *(const float4*)(A + (size_t)(r0 + m) * 256 + k0 + kk4 * 4);
            As2[m * 16 + kk4 * 4 + 0] = pack2(v.x, v.x);
            As2[m * 16 + kk4 * 4 + 1] = pack2(v.y, v.y);
            As2[m * 16 + kk4 * 4 + 2] = pack2(v.z, v.z);
            As2[m * 16 + kk4 * 4 + 3] = pack2(v.w, v.w);
        }
#pragma unroll
        for (int it = 0; it < 2; it++) {
            int f = tid + it * 256;          // 512 float4 loads of B tile
            int kk = f >> 5, j4 = f & 31;
            *(float4*)(Bs + kk * 128 + j4 * 4) =
                *(const float4*)(g_WihT + (size_t)(k0 + kk) * 768 + j0 + j4 * 4);
        }
        __syncthreads();
#pragma unroll
        for (int kk = 0; kk < 16; kk++) {
            unsigned long long a[8];
#pragma unroll
            for (int i = 0; i < 8; i++) a[i] = As2[(ty * 8 + i) * 16 + kk];
            ulonglong2 b01 = *(ulonglong2*)(Bs + kk * 128 + tx * 8);
            ulonglong2 b23 = *(ulonglong2*)(Bs + kk * 128 + tx * 8 + 4);
#pragma unroll
            for (int i = 0; i < 8; i++) {
                acc[i][0] = fma2(a[i], b01.x, acc[i][0]);
                acc[i][1] = fma2(a[i], b01.y, acc[i][1]);
                acc[i][2] = fma2(a[i], b23.x, acc[i][2]);
                acc[i][3] = fma2(a[i], b23.y, acc[i][3]);
            }
        }
        __syncthreads();
    }

    const int jb = j0 + tx * 8;
    float bias[8];
#pragma unroll
    for (int p = 0; p < 8; p++) {
        int j = jb + p;
        bias[p] = b_ih[j] + (j < 512 ? b_hh[j] : 0.0f);
    }
#pragma unroll
    for (int i = 0; i < 8; i++) {
        float o[8];
#pragma unroll
        for (int p = 0; p < 4; p++) {
            float2 v = unpack2(acc[i][p]);
            o[2 * p]     = v.x + bias[2 * p];
            o[2 * p + 1] = v.y + bias[2 * p + 1];
        }
        float* dst = g_GI + (size_t)(r0 + ty * 8 + i) * 768 + jb;
        *(float4*)dst       = make_float4(o[0], o[1], o[2], o[3]);
        *(float4*)(dst + 4) = make_float4(o[4], o[5], o[6], o[7]);
    }
}

// ---------------------------------------------------------------------------
// Recurrent kernel: one CTA per batch b (128 CTAs), 64 rows (=S) per CTA,
// h [64][256] double-buffered in SMEM for all 10 steps.
// Per step, per 64-wide d-chunk: acc_{r,z,hn}[row][d] = h . WhhT columns
// (d, 256+d, 512+d), then fused GRU activation + y readout.
__global__ void __launch_bounds__(256) rnn_kernel(const float* __restrict__ user_embs,
                                                  const float* __restrict__ b_hh,
                                                  const float* __restrict__ w_out,
                                                  const float* __restrict__ b_out,
                                                  const int* __restrict__ length,
                                                  float* __restrict__ out) {
    extern __shared__ float sm[];
    float* hbuf0 = sm;           // 16384 floats
    float* hbuf1 = sm + 16384;   // 16384
    float* wsm   = sm + 32768;   // [32 kk][3 gate][64 j] = 6144
    float* ysm   = sm + 38912;   // 64

    const int b = blockIdx.x;
    const int tid = threadIdx.x;
    const int tx = tid & 15, ty = tid >> 4;  // tx -> d groups, ty -> row groups

    // h0 = user_embs[b, clip(length[b]-1, 0)], broadcast to all 64 rows
    int idx = length[b] - 1;
    if (idx < 0) idx = 0;
    const float* u0 = user_embs + ((size_t)b * 64 + idx) * 256;
#pragma unroll 1
    for (int it = 0; it < 64; it++) {
        int t = tid + it * 256;
        hbuf0[t] = u0[t & 255];
    }
    const float bout = b_out[0];
    float* hcur = hbuf0;
    float* hnxt = hbuf1;

    for (int k = 0; k < 10; k++) {
        if (tid < 64) ysm[tid] = bout;
        float yacc[4] = {0.f, 0.f, 0.f, 0.f};

#pragma unroll 1
        for (int dc = 0; dc < 4; dc++) {
            unsigned long long ar[4][2], az[4][2], an[4][2];
#pragma unroll
            for (int i = 0; i < 4; i++) {
                ar[i][0] = ar[i][1] = 0ull;
                az[i][0] = az[i][1] = 0ull;
                an[i][0] = an[i][1] = 0ull;
            }
#pragma unroll 1
            for (int kt = 0; kt < 8; kt++) {
                __syncthreads();  // protect wsm reuse (also orders h-init / h swap)
#pragma unroll
                for (int it = 0; it < 6; it++) {
                    int f = tid + it * 256;  // 1536 float4s: [32 kk][3 g][16 j4]
                    int kk = f / 48;
                    int rem = f - kk * 48;
                    int g = rem >> 4;
                    int j4 = rem & 15;
                    *(float4*)(wsm + kk * 192 + g * 64 + j4 * 4) =
                        *(const float4*)(g_WhhT + (size_t)(kt * 32 + kk) * 768 +
                                         g * 256 + dc * 64 + j4 * 4);
                }
                __syncthreads();
#pragma unroll
                for (int kk4 = 0; kk4 < 8; kk4++) {
                    float4 av[4];
#pragma unroll
                    for (int i = 0; i < 4; i++)
                        av[i] = *(const float4*)(hcur + (ty * 4 + i) * 256 +
                                                 kt * 32 + kk4 * 4);
                    const float* avf = (const float*)av;
#pragma unroll
                    for (int c = 0; c < 4; c++) {
                        const int kk = kk4 * 4 + c;
                        ulonglong2 br = *(ulonglong2*)(wsm + kk * 192 + tx * 4);
                        ulonglong2 bz = *(ulonglong2*)(wsm + kk * 192 + 64 + tx * 4);
                        ulonglong2 bn = *(ulonglong2*)(wsm + kk * 192 + 128 + tx * 4);
#pragma unroll
                        for (int i = 0; i < 4; i++) {
                            unsigned long long a2 = pack2(avf[i * 4 + c], avf[i * 4 + c]);
                            ar[i][0] = fma2(a2, br.x, ar[i][0]);
                            ar[i][1] = fma2(a2, br.y, ar[i][1]);
                            az[i][0] = fma2(a2, bz.x, az[i][0]);
                            az[i][1] = fma2(a2, bz.y, az[i][1]);
                            an[i][0] = fma2(a2, bn.x, an[i][0]);
                            an[i][1] = fma2(a2, bn.y, an[i][1]);
                        }
                    }
                }
            }

            // fused GRU activation for this 64-wide d-chunk
            const int d = dc * 64 + tx * 4;
            float4 bh4 = *(const float4*)(b_hh + 512 + d);
            float4 wo4 = *(const float4*)(w_out + d);
            const float* bhf = (const float*)&bh4;
            const float* wof = (const float*)&wo4;
#pragma unroll
            for (int i = 0; i < 4; i++) {
                const int row = ty * 4 + i;
                const int n = b * 64 + row;
                const float* gi = g_GI + (size_t)(n * 10 + k) * 768;
                float4 gr4 = *(const float4*)(gi + d);
                float4 gz4 = *(const float4*)(gi + 256 + d);
                float4 gn4 = *(const float4*)(gi + 512 + d);
                float4 ho4 = *(const float4*)(hcur + row * 256 + d);
                const float* grf = (const float*)&gr4;
                const float* gzf = (const float*)&gz4;
                const float* gnf = (const float*)&gn4;
                const float* hof = (const float*)&ho4;
                float arf[4], azf[4], anf[4];
                float2 p;
                p = unpack2(ar[i][0]); arf[0] = p.x; arf[1] = p.y;
                p = unpack2(ar[i][1]); arf[2] = p.x; arf[3] = p.y;
                p = unpack2(az[i][0]); azf[0] = p.x; azf[1] = p.y;
                p = unpack2(az[i][1]); azf[2] = p.x; azf[3] = p.y;
                p = unpack2(an[i][0]); anf[0] = p.x; anf[1] = p.y;
                p = unpack2(an[i][1]); anf[2] = p.x; anf[3] = p.y;
                float hv[4];
#pragma unroll
                for (int c = 0; c < 4; c++) {
                    float r = 1.0f / (1.0f + expf(-(grf[c] + arf[c])));
                    float z = 1.0f / (1.0f + expf(-(gzf[c] + azf[c])));
                    float hn = anf[c] + bhf[c];
                    float nv = tanhf(gnf[c] + r * hn);
                    hv[c] = (1.0f - z) * nv + z * hof[c];
                    yacc[i] += hv[c] * wof[c];
                }
                *(float4*)(hnxt + row * 256 + d) = make_float4(hv[0], hv[1], hv[2], hv[3]);
            }
        }

        // y readout reduction across d (threads sharing a row)
#pragma unroll
        for (int i = 0; i < 4; i++) atomicAdd(&ysm[ty * 4 + i], yacc[i]);
        __syncthreads();
        if (tid < 64) out[(size_t)(b * 64 + tid) * 10 + k] = ysm[tid];
        float* tmp = hcur; hcur = hnxt; hnxt = tmp;
        __syncthreads();
    }
}

// ---------------------------------------------------------------------------
extern "C" void kernel_launch(void* const* d_in, const int* in_sizes, int n_in,
                              void* d_out, int out_size) {
    (void)in_sizes; (void)n_in; (void)out_size;
    const float* item_embs = (const float*)d_in[0];  // [128,64,10,256]
    const float* user_embs = (const float*)d_in[1];  // [128,64,256]
    const float* W_ih      = (const float*)d_in[2];  // [768,512]
    const float* W_hh      = (const float*)d_in[3];  // [768,256]
    const float* b_ih      = (const float*)d_in[4];  // [768]
    const float* b_hh      = (const float*)d_in[5];  // [768]
    const float* w_out     = (const float*)d_in[6];  // [256]
    const float* b_out     = (const float*)d_in[7];  // scalar
    const int*   length    = (const int*)d_in[8];    // [128]
    float* out = (float*)d_out;                      // [128,64,10]

    prep_kernel<<<768, 256>>>(W_ih, W_hh);

    dim3 gg(640, 6);  // 81920/128 x 768/128
    gi_gemm<<<gg, 256>>>(item_embs, b_ih, b_hh);

    const int smem = (2 * 64 * 256 + 32 * 192 + 64) * 4;  // 155,904 B
    cudaFuncSetAttribute(rnn_kernel, cudaFuncAttributeMaxDynamicSharedMemorySize, smem);
    rnn_kernel<<<128, 256, smem>>>(user_embs, b_hh, w_out, b_out, length, out);
}

// round 5
// speedup vs baseline: 1.4971x; 1.4971x over previous
#include <cuda_runtime.h>
#include <cstdint>
#include <math.h>

// SlatewiseGRU: B=128, S=64, K=10, D=256.
// Input second half is zeros => threshold mask dead, GI GEMM hoisted.
// R3/R4: both GEMMs on mma.sync m16n8k8 TF32 (3xTF32 split = fp32 accuracy).
// tcgen05 unavailable: harness compiles via compute_103 virtual arch.
// R4 = R3 resubmitted verbatim (R3 bench was an infra failure, no signal).

// ---------------------------------------------------------------------------
static __device__ __forceinline__ uint32_t smem_u32(const void* p) {
    uint32_t a;
    asm("{ .reg .u64 t; cvta.to.shared.u64 t, %1; cvt.u32.u64 %0, t; }"
        : "=r"(a) : "l"(p));
    return a;
}
static __device__ __forceinline__ void cp16(uint32_t dst, const void* src) {
    asm volatile("cp.async.cg.shared.global [%0], [%1], 16;"
                 :: "r"(dst), "l"(src));
}
static __device__ __forceinline__ void cp_commit() {
    asm volatile("cp.async.commit_group;" ::: "memory");
}
static __device__ __forceinline__ void cp_wait1() {
    asm volatile("cp.async.wait_group 1;" ::: "memory");
}
static __device__ __forceinline__ void cp_wait0() {
    asm volatile("cp.async.wait_group 0;" ::: "memory");
}
static __device__ __forceinline__ uint32_t tf32_hi(float x) {
    uint32_t u;
    asm("cvt.rna.tf32.f32 %0, %1;" : "=r"(u) : "f"(x));
    return u;
}
static __device__ __forceinline__ uint32_t tf32_lo(float x) {
    uint32_t h = tf32_hi(x);
    return tf32_hi(x - __uint_as_float(h));
}
// D += A(16x8) * B(8x8), tf32 inputs, f32 accum.
static __device__ __forceinline__ void mma168(float& d0, float& d1, float& d2,
                                              float& d3, uint32_t a0, uint32_t a1,
                                              uint32_t a2, uint32_t a3,
                                              uint32_t b0, uint32_t b1) {
    asm("mma.sync.aligned.m16n8k8.row.col.f32.tf32.tf32.f32 "
        "{%0,%1,%2,%3}, {%4,%5,%6,%7}, {%8,%9}, {%0,%1,%2,%3};"
        : "+f"(d0), "+f"(d1), "+f"(d2), "+f"(d3)
        : "r"(a0), "r"(a1), "r"(a2), "r"(a3), "r"(b0), "r"(b1));
}

// Scratch (device globals: allocation-free per harness rules)
__device__ float g_GI[62914560];      // [81920][768] input gates (+biases)
__device__ float g_WihT_hi[196608];   // [256][768] tf32-hi of W_ih[:, :256]^T
__device__ float g_WihT_lo[196608];
__device__ float g_WhhT_hi[196608];   // [256][768] tf32-hi of W_hh^T
__device__ float g_WhhT_lo[196608];

// ---------------------------------------------------------------------------
__global__ void prep_kernel(const float* __restrict__ W_ih,
                            const float* __restrict__ W_hh) {
    int idx = blockIdx.x * 256 + threadIdx.x;   // 196608 total
    int k = idx / 768;
    int j = idx - k * 768;
    float wi = W_ih[(size_t)j * 512 + k];
    uint32_t h = tf32_hi(wi);
    g_WihT_hi[idx] = __uint_as_float(h);
    g_WihT_lo[idx] = __uint_as_float(tf32_hi(wi - __uint_as_float(h)));
    float wh = W_hh[(size_t)j * 256 + k];
    uint32_t h2 = tf32_hi(wh);
    g_WhhT_hi[idx] = __uint_as_float(h2);
    g_WhhT_lo[idx] = __uint_as_float(tf32_hi(wh - __uint_as_float(h2)));
}

// ---------------------------------------------------------------------------
// GI[r, j] = sum_k items[r,k] * W_ih[j,k] (+ bias), via 3xTF32 mma.sync.
// Block tile 128x128, 8 warps (2m x 4n), warp tile 64x32 (mt4 x nt4).
// K chunked by 16, cp.async double-buffered.
__global__ void __launch_bounds__(256, 2) gi_tc(const float* __restrict__ A,
                                                const float* __restrict__ b_ih,
                                                const float* __restrict__ b_hh) {
    extern __shared__ float smf[];
    // layout (floats): A bufs 2x2560 @0 ; B bufs [hi0,lo0,hi1,lo1] 4x2176 @5120
    const uint32_t sbase = smem_u32(smf);
    const int tid = threadIdx.x;
    const int lane = tid & 31, w = tid >> 5;
    const int gid = lane >> 2, tidg = lane & 3;
    const int mbase = (w >> 2) * 64, nbase = (w & 3) * 32;
    const int r0 = blockIdx.x * 128, j0 = blockIdx.y * 128;

    float acc[4][4][4];
#pragma unroll
    for (int mt = 0; mt < 4; mt++)
#pragma unroll
        for (int nt = 0; nt < 4; nt++)
#pragma unroll
            for (int c = 0; c < 4; c++) acc[mt][nt][c] = 0.0f;

    // issue staging for chunk c into parity buffers
    auto issue = [&](int c) {
        int p = c & 1;
        uint32_t aA = sbase + (uint32_t)(p * 2560) * 4;
        uint32_t aBh = sbase + (uint32_t)(5120 + p * 4352) * 4;
        uint32_t aBl = aBh + 2176 * 4;
#pragma unroll
        for (int it = 0; it < 2; it++) {
            int f = tid + it * 256;
            int m = f >> 2, q = f & 3;
            cp16(aA + (uint32_t)(m * 20 + q * 4) * 4,
                 A + (size_t)(r0 + m) * 256 + c * 16 + q * 4);
        }
#pragma unroll
        for (int it = 0; it < 2; it++) {
            int f = tid + it * 256;
            int kk = f >> 5, j4 = f & 31;
            size_t src = (size_t)(c * 16 + kk) * 768 + j0 + j4 * 4;
            cp16(aBh + (uint32_t)(kk * 136 + j4 * 4) * 4, g_WihT_hi + src);
            cp16(aBl + (uint32_t)(kk * 136 + j4 * 4) * 4, g_WihT_lo + src);
        }
        cp_commit();
    };

    issue(0);
    for (int c = 0; c < 16; c++) {
        if (c + 1 < 16) { issue(c + 1); cp_wait1(); } else { cp_wait0(); }
        __syncthreads();
        const float* As = smf + (c & 1) * 2560;
        const float* Bh = smf + 5120 + (c & 1) * 4352;
        const float* Bl = Bh + 2176;
#pragma unroll
        for (int ks = 0; ks < 2; ks++) {
            uint32_t bh[4][2], bl[4][2];
#pragma unroll
            for (int nt = 0; nt < 4; nt++) {
                const float* bp = Bh + (ks * 8 + tidg) * 136 + nbase + 8 * nt + gid;
                bh[nt][0] = __float_as_uint(bp[0]);
                bh[nt][1] = __float_as_uint(bp[4 * 136]);
                const float* lp = Bl + (ks * 8 + tidg) * 136 + nbase + 8 * nt + gid;
                bl[nt][0] = __float_as_uint(lp[0]);
                bl[nt][1] = __float_as_uint(lp[4 * 136]);
            }
#pragma unroll
            for (int mt = 0; mt < 4; mt++) {
                const float* ap = As + (mbase + 16 * mt + gid) * 20 + ks * 8 + tidg;
                float x0 = ap[0], x1 = ap[8 * 20], x2 = ap[4], x3 = ap[8 * 20 + 4];
                uint32_t ah0 = tf32_hi(x0), ah1 = tf32_hi(x1);
                uint32_t ah2 = tf32_hi(x2), ah3 = tf32_hi(x3);
                uint32_t al0 = tf32_hi(x0 - __uint_as_float(ah0));
                uint32_t al1 = tf32_hi(x1 - __uint_as_float(ah1));
                uint32_t al2 = tf32_hi(x2 - __uint_as_float(ah2));
                uint32_t al3 = tf32_hi(x3 - __uint_as_float(ah3));
#pragma unroll
                for (int nt = 0; nt < 4; nt++) {
                    mma168(acc[mt][nt][0], acc[mt][nt][1], acc[mt][nt][2],
                           acc[mt][nt][3], ah0, ah1, ah2, ah3, bh[nt][0], bh[nt][1]);
                    mma168(acc[mt][nt][0], acc[mt][nt][1], acc[mt][nt][2],
                           acc[mt][nt][3], al0, al1, al2, al3, bh[nt][0], bh[nt][1]);
                    mma168(acc[mt][nt][0], acc[mt][nt][1], acc[mt][nt][2],
                           acc[mt][nt][3], ah0, ah1, ah2, ah3, bl[nt][0], bl[nt][1]);
                }
            }
        }
        __syncthreads();  // buffer reuse guard before next issue
    }

    // epilogue: add bias, store float2s
    const bool addh = (j0 + nbase) < 512;
    float2 bias[4];
#pragma unroll
    for (int nt = 0; nt < 4; nt++) {
        int j = j0 + nbase + 8 * nt + 2 * tidg;
        float2 v = *(const float2*)(b_ih + j);
        if (addh) {
            float2 h2 = *(const float2*)(b_hh + j);
            v.x += h2.x; v.y += h2.y;
        }
        bias[nt] = v;
    }
#pragma unroll
    for (int mt = 0; mt < 4; mt++)
#pragma unroll
        for (int rh = 0; rh < 2; rh++) {
            int row = mbase + 16 * mt + 8 * rh + gid;
            float* dst = g_GI + (size_t)(r0 + row) * 768 + j0 + nbase;
#pragma unroll
            for (int nt = 0; nt < 4; nt++) {
                float2 o;
                o.x = acc[mt][nt][2 * rh] + bias[nt].x;
                o.y = acc[mt][nt][2 * rh + 1] + bias[nt].y;
                *(float2*)(dst + 8 * nt + 2 * tidg) = o;
            }
        }
}

// ---------------------------------------------------------------------------
// RNN: one CTA per batch (128 CTAs, 512 threads = 16 warps).
// h [64][260] fp32 in SMEM; warp w owns d in [16w, 16w+16) across all 3 gates
// => epilogue fully in-warp. Weights (pre-split hi/lo) staged per k8-chunk
// via cp.async, double-buffered.
__global__ void __launch_bounds__(512) rnn_tc(const float* __restrict__ user_embs,
                                              const float* __restrict__ b_hh,
                                              const float* __restrict__ w_out,
                                              const float* __restrict__ b_out,
                                              const int* __restrict__ length,
                                              float* __restrict__ out) {
    extern __shared__ float smf[];
    float* hsm = smf;                 // [64][260] = 16640
    float* wbb = smf + 16640;         // 4 x 6208: [hi0, lo0, hi1, lo1]
    float* ysm = smf + 41472;         // [64]
    const uint32_t sbase = smem_u32(smf);

    const int b = blockIdx.x;
    const int tid = threadIdx.x;
    const int lane = tid & 31, w = tid >> 5;
    const int gid = lane >> 2, tidg = lane & 3;
    const int dbase = w * 16;

    // h0 = user_embs[b, clip(len-1,0)] broadcast to 64 rows
    int hidx = length[b] - 1;
    if (hidx < 0) hidx = 0;
    const float* u0 = user_embs + ((size_t)b * 64 + hidx) * 256;
    for (int i = tid; i < 64 * 256; i += 512)
        hsm[(i >> 8) * 260 + (i & 255)] = u0[i & 255];
    const float bout = b_out[0];
    if (tid < 64) ysm[tid] = bout;

    float2 bhn[2], wo[2];
#pragma unroll
    for (int nt = 0; nt < 2; nt++) {
        int d = dbase + 8 * nt + 2 * tidg;
        bhn[nt] = *(const float2*)(b_hh + 512 + d);
        wo[nt] = *(const float2*)(w_out + d);
    }

    auto issue = [&](int c) {
        int p = c & 1;
        uint32_t aH = sbase + (uint32_t)(16640 + p * 12416) * 4;
        uint32_t aL = aH + 6208 * 4;
#pragma unroll
        for (int it = 0; it < 3; it++) {
            int f = tid + it * 512;            // 1536 float4s: [8 kk][192 j4]
            int kk = f / 192;
            int j4 = f - kk * 192;
            size_t src = (size_t)(c * 8 + kk) * 768 + j4 * 4;
            uint32_t doff = (uint32_t)(kk * 776 + j4 * 4) * 4;
            cp16(aH + doff, g_WhhT_hi + src);
            cp16(aL + doff, g_WhhT_lo + src);
        }
        cp_commit();
    };

    float acc[4][3][2][4];

    for (int k = 0; k < 10; k++) {
#pragma unroll
        for (int mt = 0; mt < 4; mt++)
#pragma unroll
            for (int g = 0; g < 3; g++)
#pragma unroll
                for (int nt = 0; nt < 2; nt++)
#pragma unroll
                    for (int c = 0; c < 4; c++) acc[mt][g][nt][c] = 0.0f;

        issue(0);
        for (int c = 0; c < 32; c++) {
            if (c + 1 < 32) { issue(c + 1); cp_wait1(); } else { cp_wait0(); }
            __syncthreads();
            const float* whi = wbb + (c & 1) * 12416;
            const float* wlo = whi + 6208;
#pragma unroll
            for (int pass = 0; pass < 3; pass++) {
                const float* wb = (pass == 2) ? wlo : whi;
                uint32_t bfr[6][2];
#pragma unroll
                for (int g = 0; g < 3; g++)
#pragma unroll
                    for (int nt = 0; nt < 2; nt++) {
                        int n = g * 256 + dbase + 8 * nt + gid;
                        const float* bp = wb + tidg * 776 + n;
                        bfr[g * 2 + nt][0] = __float_as_uint(bp[0]);
                        bfr[g * 2 + nt][1] = __float_as_uint(bp[4 * 776]);
                    }
#pragma unroll
                for (int mt = 0; mt < 4; mt++) {
                    const float* ap = hsm + (16 * mt + gid) * 260 + c * 8 + tidg;
                    float x0 = ap[0], x1 = ap[8 * 260];
                    float x2 = ap[4], x3 = ap[8 * 260 + 4];
                    uint32_t a0, a1, a2, a3;
                    if (pass == 1) {
                        a0 = tf32_lo(x0); a1 = tf32_lo(x1);
                        a2 = tf32_lo(x2); a3 = tf32_lo(x3);
                    } else {
                        a0 = tf32_hi(x0); a1 = tf32_hi(x1);
                        a2 = tf32_hi(x2); a3 = tf32_hi(x3);
                    }
#pragma unroll
                    for (int g = 0; g < 3; g++)
#pragma unroll
                        for (int nt = 0; nt < 2; nt++)
                            mma168(acc[mt][g][nt][0], acc[mt][g][nt][1],
                                   acc[mt][g][nt][2], acc[mt][g][nt][3],
                                   a0, a1, a2, a3,
                                   bfr[g * 2 + nt][0], bfr[g * 2 + nt][1]);
                }
            }
            __syncthreads();  // buffer reuse guard; last iter: pre-epilogue guard
        }

        // fused GRU epilogue (each (row,d) cell owned by exactly one thread)
#pragma unroll
        for (int mt = 0; mt < 4; mt++)
#pragma unroll
            for (int rh = 0; rh < 2; rh++) {
                int row = 16 * mt + 8 * rh + gid;
                const float* gi = g_GI + ((size_t)(b * 64 + row) * 10 + k) * 768;
                float yp = 0.0f;
#pragma unroll
                for (int nt = 0; nt < 2; nt++) {
                    int d = dbase + 8 * nt + 2 * tidg;
                    float2 gr = *(const float2*)(gi + d);
                    float2 gz = *(const float2*)(gi + 256 + d);
                    float2 gn = *(const float2*)(gi + 512 + d);
                    float2 ho = *(const float2*)(hsm + row * 260 + d);
                    int c0 = rh * 2;
                    float r0v = 1.0f / (1.0f + expf(-(gr.x + acc[mt][0][nt][c0])));
                    float r1v = 1.0f / (1.0f + expf(-(gr.y + acc[mt][0][nt][c0 + 1])));
                    float z0v = 1.0f / (1.0f + expf(-(gz.x + acc[mt][1][nt][c0])));
                    float z1v = 1.0f / (1.0f + expf(-(gz.y + acc[mt][1][nt][c0 + 1])));
                    float hn0 = acc[mt][2][nt][c0] + bhn[nt].x;
                    float hn1 = acc[mt][2][nt][c0 + 1] + bhn[nt].y;
                    float n0 = tanhf(gn.x + r0v * hn0);
                    float n1 = tanhf(gn.y + r1v * hn1);
                    float h0n = (1.0f - z0v) * n0 + z0v * ho.x;
                    float h1n = (1.0f - z1v) * n1 + z1v * ho.y;
                    *(float2*)(hsm + row * 260 + d) = make_float2(h0n, h1n);
                    yp += h0n * wo[nt].x + h1n * wo[nt].y;
                }
                yp += __shfl_xor_sync(0xffffffffu, yp, 1);
                yp += __shfl_xor_sync(0xffffffffu, yp, 2);
                if (tidg == 0) atomicAdd(&ysm[row], yp);
            }
        __syncthreads();
        if (tid < 64) {
            out[((size_t)(b * 64) + tid) * 10 + k] = ysm[tid];
            ysm[tid] = bout;
        }
        // next step's first chunk barrier orders h writes / ysm reset vs reads
    }
}

// ---------------------------------------------------------------------------
extern "C" void kernel_launch(void* const* d_in, const int* in_sizes, int n_in,
                              void* d_out, int out_size) {
    (void)in_sizes; (void)n_in; (void)out_size;
    const float* item_embs = (const float*)d_in[0];  // [128,64,10,256]
    const float* user_embs = (const float*)d_in[1];  // [128,64,256]
    const float* W_ih      = (const float*)d_in[2];  // [768,512]
    const float* W_hh      = (const float*)d_in[3];  // [768,256]
    const float* b_ih      = (const float*)d_in[4];  // [768]
    const float* b_hh      = (const float*)d_in[5];  // [768]
    const float* w_out     = (const float*)d_in[6];  // [256]
    const float* b_out     = (const float*)d_in[7];  // scalar
    const int*   length    = (const int*)d_in[8];    // [128]
    float* out = (float*)d_out;                      // [128,64,10]

    prep_kernel<<<768, 256>>>(W_ih, W_hh);

    const int gi_smem = 55296;  // (2*2560 + 4*2176) * 4
    cudaFuncSetAttribute(gi_tc, cudaFuncAttributeMaxDynamicSharedMemorySize,
                         gi_smem);
    dim3 gg(640, 6);  // 81920/128 x 768/128
    gi_tc<<<gg, 256, gi_smem>>>(item_embs, b_ih, b_hh);

    const int rnn_smem = 166144;  // (16640 + 4*6208 + 64) * 4
    cudaFuncSetAttribute(rnn_tc, cudaFuncAttributeMaxDynamicSharedMemorySize,
                         rnn_smem);
    rnn_tc<<<128, 512, rnn_smem>>>(user_embs, b_hh, w_out, b_out, length, out);
}

// round 6
// speedup vs baseline: 2.6224x; 1.7517x over previous
#include <cuda_runtime.h>
#include <cuda_fp16.h>
#include <cstdint>
#include <math.h>

// SlatewiseGRU: B=128, S=64, K=10, D=256.
// Input second half is zeros => threshold mask dead, GI GEMM hoisted.
// R5: fp16 m16n8k16 mma with 3-term error-compensated split (fp32-level
// accuracy); halves mma instruction count vs tf32 m16n8k8 (R4).

// ---------------------------------------------------------------------------
static __device__ __forceinline__ uint32_t smem_u32(const void* p) {
    uint32_t a;
    asm("{ .reg .u64 t; cvta.to.shared.u64 t, %1; cvt.u32.u64 %0, t; }"
        : "=r"(a) : "l"(p));
    return a;
}
static __device__ __forceinline__ void cp16(uint32_t dst, const void* src) {
    asm volatile("cp.async.cg.shared.global [%0], [%1], 16;"
                 :: "r"(dst), "l"(src));
}
static __device__ __forceinline__ void cp_commit() {
    asm volatile("cp.async.commit_group;" ::: "memory");
}
static __device__ __forceinline__ void cp_wait1() {
    asm volatile("cp.async.wait_group 1;" ::: "memory");
}
static __device__ __forceinline__ void cp_wait0() {
    asm volatile("cp.async.wait_group 0;" ::: "memory");
}
// pack two fp32 into f16x2 reg: low half = x0 (even k), high half = x1
static __device__ __forceinline__ uint32_t pack_h2(float x0, float x1) {
    uint32_t r;
    asm("cvt.rn.f16x2.f32 %0, %1, %2;" : "=r"(r) : "f"(x1), "f"(x0));
    return r;
}
// split (x0,x1) into fp16 hi pair + fp16 lo (residual) pair
static __device__ __forceinline__ uint32_t split_h2(float x0, float x1,
                                                    uint32_t& lo) {
    uint32_t hi = pack_h2(x0, x1);
    half2 h = *reinterpret_cast<half2*>(&hi);
    float2 b = __half22float2(h);
    lo = pack_h2(x0 - b.x, x1 - b.y);
    return hi;
}
// D += A(16x16) * B(16x8), fp16 inputs, fp32 accum.
static __device__ __forceinline__ void mma16816(float& d0, float& d1, float& d2,
                                                float& d3, uint32_t a0,
                                                uint32_t a1, uint32_t a2,
                                                uint32_t a3, uint32_t b0,
                                                uint32_t b1) {
    asm("mma.sync.aligned.m16n8k16.row.col.f32.f16.f16.f32 "
        "{%0,%1,%2,%3}, {%4,%5,%6,%7}, {%8,%9}, {%0,%1,%2,%3};"
        : "+f"(d0), "+f"(d1), "+f"(d2), "+f"(d3)
        : "r"(a0), "r"(a1), "r"(a2), "r"(a3), "r"(b0), "r"(b1));
}

// Scratch (device globals: allocation-free per harness rules)
__device__ float g_GI[62914560];         // [81920][768] input gates (+biases)
__device__ uint32_t g_IPk_hi[10485760];  // [81920 rows][128 kpair] f16x2 items
__device__ uint32_t g_IPk_lo[10485760];
__device__ uint32_t g_WihPk_hi[98304];   // [128 kpair][768 j] f16x2 W_ih^T
__device__ uint32_t g_WihPk_lo[98304];
__device__ uint32_t g_WhhPk_hi[98304];   // [128 kpair][768 j] f16x2 W_hh^T
__device__ uint32_t g_WhhPk_lo[98304];

// ---------------------------------------------------------------------------
__global__ void prep_weights(const float* __restrict__ W_ih,
                             const float* __restrict__ W_hh) {
    int idx = blockIdx.x * 256 + threadIdx.x;  // 98304 = 128 kpair x 768 j
    if (idx >= 98304) return;
    int kp = idx / 768;
    int j = idx - kp * 768;
    {
        float x0 = W_ih[(size_t)j * 512 + 2 * kp];
        float x1 = W_ih[(size_t)j * 512 + 2 * kp + 1];
        uint32_t lo, hi = split_h2(x0, x1, lo);
        g_WihPk_hi[idx] = hi;
        g_WihPk_lo[idx] = lo;
    }
    {
        float x0 = W_hh[(size_t)j * 256 + 2 * kp];
        float x1 = W_hh[(size_t)j * 256 + 2 * kp + 1];
        uint32_t lo, hi = split_h2(x0, x1, lo);
        g_WhhPk_hi[idx] = hi;
        g_WhhPk_lo[idx] = lo;
    }
}

__global__ void prep_items(const float* __restrict__ A) {
    // 81920 rows x 128 kpairs = 10485760 pairs; 10240 blocks x 256 thr x 4
    int base = blockIdx.x * 256 + threadIdx.x;
#pragma unroll
    for (int it = 0; it < 4; it++) {
        int i = base + it * 2621440;
        float2 v = ((const float2*)A)[i];
        uint32_t lo, hi = split_h2(v.x, v.y, lo);
        g_IPk_hi[i] = hi;
        g_IPk_lo[i] = lo;
    }
}

// ---------------------------------------------------------------------------
// GI[r, j] = sum_k items[r,k] * W_ih[j,k] (+ bias), 3x fp16 split mma.
// Block tile 128x128, 8 warps (2m x 4n), warp tile 64x32.
// K chunked by 32 (16 kpairs), cp.async double-buffered, pre-split operands.
__global__ void __launch_bounds__(256, 2) gi_tc(const float* __restrict__ b_ih,
                                                const float* __restrict__ b_hh) {
    extern __shared__ uint32_t smu[];
    // A: (2p+h)*2560 : [128 m][20] (16 kpair + 4 pad)
    // B: 10240 + (2p+h)*2112 : [16 kpair][132]
    const uint32_t sbase = smem_u32(smu);
    const int tid = threadIdx.x;
    const int lane = tid & 31, w = tid >> 5;
    const int gid = lane >> 2, tidg = lane & 3;
    const int mbase = (w >> 2) * 64, nbase = (w & 3) * 32;
    const int r0 = blockIdx.x * 128, j0 = blockIdx.y * 128;

    float acc[4][4][4];
#pragma unroll
    for (int mt = 0; mt < 4; mt++)
#pragma unroll
        for (int nt = 0; nt < 4; nt++)
#pragma unroll
            for (int c = 0; c < 4; c++) acc[mt][nt][c] = 0.0f;

    auto issue = [&](int c) {
        int p = c & 1;
        uint32_t aA = sbase + (uint32_t)(2 * p * 2560) * 4;
        uint32_t aB = sbase + (uint32_t)(10240 + 2 * p * 2112) * 4;
#pragma unroll
        for (int it = 0; it < 4; it++) {
            int f = tid + it * 256;           // 1024 cp16: [h][128 m][4 k4]
            int h = f >> 9, rem = f & 511;
            int m = rem >> 2, k4 = rem & 3;
            const uint32_t* src = (h ? g_IPk_lo : g_IPk_hi) +
                                  (size_t)(r0 + m) * 128 + c * 16 + k4 * 4;
            cp16(aA + (uint32_t)(h * 2560 + m * 20 + k4 * 4) * 4, src);
        }
#pragma unroll
        for (int it = 0; it < 4; it++) {
            int f = tid + it * 256;           // 1024 cp16: [h][16 kp][32 j4]
            int h = f >> 9, rem = f & 511;
            int kp = rem >> 5, j4 = rem & 31;
            const uint32_t* src = (h ? g_WihPk_lo : g_WihPk_hi) +
                                  (size_t)(c * 16 + kp) * 768 + j0 + j4 * 4;
            cp16(aB + (uint32_t)(h * 2112 + kp * 132 + j4 * 4) * 4, src);
        }
        cp_commit();
    };

    issue(0);
    for (int c = 0; c < 8; c++) {
        if (c + 1 < 8) { issue(c + 1); cp_wait1(); } else { cp_wait0(); }
        __syncthreads();
        const uint32_t* Ah = smu + 2 * (c & 1) * 2560;
        const uint32_t* Al = Ah + 2560;
        const uint32_t* Bh = smu + 10240 + 2 * (c & 1) * 2112;
        const uint32_t* Bl = Bh + 2112;
#pragma unroll
        for (int ks = 0; ks < 2; ks++) {
            const int kp0 = 8 * ks + tidg, kp1 = kp0 + 4;
            uint32_t bh[4][2], bl[4][2];
#pragma unroll
            for (int nt = 0; nt < 4; nt++) {
                int j = nbase + 8 * nt + gid;
                bh[nt][0] = Bh[kp0 * 132 + j];
                bh[nt][1] = Bh[kp1 * 132 + j];
                bl[nt][0] = Bl[kp0 * 132 + j];
                bl[nt][1] = Bl[kp1 * 132 + j];
            }
#pragma unroll
            for (int mt = 0; mt < 4; mt++) {
                int row = mbase + 16 * mt + gid;
                uint32_t ah0 = Ah[row * 20 + kp0];
                uint32_t ah1 = Ah[(row + 8) * 20 + kp0];
                uint32_t ah2 = Ah[row * 20 + kp1];
                uint32_t ah3 = Ah[(row + 8) * 20 + kp1];
                uint32_t al0 = Al[row * 20 + kp0];
                uint32_t al1 = Al[(row + 8) * 20 + kp0];
                uint32_t al2 = Al[row * 20 + kp1];
                uint32_t al3 = Al[(row + 8) * 20 + kp1];
#pragma unroll
                for (int nt = 0; nt < 4; nt++) {
                    mma16816(acc[mt][nt][0], acc[mt][nt][1], acc[mt][nt][2],
                             acc[mt][nt][3], ah0, ah1, ah2, ah3,
                             bh[nt][0], bh[nt][1]);
                    mma16816(acc[mt][nt][0], acc[mt][nt][1], acc[mt][nt][2],
                             acc[mt][nt][3], al0, al1, al2, al3,
                             bh[nt][0], bh[nt][1]);
                    mma16816(acc[mt][nt][0], acc[mt][nt][1], acc[mt][nt][2],
                             acc[mt][nt][3], ah0, ah1, ah2, ah3,
                             bl[nt][0], bl[nt][1]);
                }
            }
        }
        __syncthreads();  // buffer reuse guard before next issue
    }

    // epilogue: add bias, store float2s
    const bool addh = (j0 + nbase) < 512;
    float2 bias[4];
#pragma unroll
    for (int nt = 0; nt < 4; nt++) {
        int j = j0 + nbase + 8 * nt + 2 * tidg;
        float2 v = *(const float2*)(b_ih + j);
        if (addh) {
            float2 h2 = *(const float2*)(b_hh + j);
            v.x += h2.x; v.y += h2.y;
        }
        bias[nt] = v;
    }
#pragma unroll
    for (int mt = 0; mt < 4; mt++)
#pragma unroll
        for (int rh = 0; rh < 2; rh++) {
            int row = mbase + 16 * mt + 8 * rh + gid;
            float* dst = g_GI + (size_t)(r0 + row) * 768 + j0 + nbase;
#pragma unroll
            for (int nt = 0; nt < 4; nt++) {
                float2 o;
                o.x = acc[mt][nt][2 * rh] + bias[nt].x;
                o.y = acc[mt][nt][2 * rh + 1] + bias[nt].y;
                *(float2*)(dst + 8 * nt + 2 * tidg) = o;
            }
        }
}

// ---------------------------------------------------------------------------
// RNN: one CTA per batch (128 CTAs, 512 threads = 16 warps).
// h kept in SMEM as f16x2 hi/lo pairs (written by epilogue); warp w owns
// d in [16w, 16w+16) across all 3 gates => epilogue fully in-warp.
// Pre-split weights staged per k16-chunk via cp.async, double-buffered.
__global__ void __launch_bounds__(512) rnn_tc(const float* __restrict__ user_embs,
                                              const float* __restrict__ b_hh,
                                              const float* __restrict__ w_out,
                                              const float* __restrict__ b_out,
                                              const int* __restrict__ length,
                                              float* __restrict__ out) {
    extern __shared__ uint32_t smu[];
    uint32_t* hsm_hi = smu;            // [64][132] (128 kpair + 4 pad)
    uint32_t* hsm_lo = smu + 8448;
    // wbufs @16896 + (2p+h)*6176 : [8 kpair][772]
    float* ysm = (float*)(smu + 41600);  // [64]
    const uint32_t sbase = smem_u32(smu);

    const int b = blockIdx.x;
    const int tid = threadIdx.x;
    const int lane = tid & 31, w = tid >> 5;
    const int gid = lane >> 2, tidg = lane & 3;
    const int dbase = w * 16;

    // h0 = user_embs[b, clip(len-1,0)] broadcast to 64 rows, split to f16 hi/lo
    int hidx = length[b] - 1;
    if (hidx < 0) hidx = 0;
    const float* u0 = user_embs + ((size_t)b * 64 + hidx) * 256;
    for (int i = tid; i < 64 * 128; i += 512) {
        int row = i >> 7, kp = i & 127;
        float2 v = *(const float2*)(u0 + 2 * kp);
        uint32_t lo, hi = split_h2(v.x, v.y, lo);
        hsm_hi[row * 132 + kp] = hi;
        hsm_lo[row * 132 + kp] = lo;
    }
    const float bout = b_out[0];
    if (tid < 64) ysm[tid] = bout;

    float2 bhn[2], wo[2];
#pragma unroll
    for (int nt = 0; nt < 2; nt++) {
        int d = dbase + 8 * nt + 2 * tidg;
        bhn[nt] = *(const float2*)(b_hh + 512 + d);
        wo[nt] = *(const float2*)(w_out + d);
    }

    auto issue = [&](int c) {
        int p = c & 1;
#pragma unroll
        for (int it = 0; it < 6; it++) {
            int f = tid + it * 512;        // 3072 cp16: [h][8 kk][192 j4]
            int h = f / 1536, rem = f - h * 1536;
            int kk = rem / 192, j4 = rem - kk * 192;
            const uint32_t* src = (h ? g_WhhPk_lo : g_WhhPk_hi) +
                                  (size_t)(c * 8 + kk) * 768 + j4 * 4;
            cp16(sbase +
                     (uint32_t)(16896 + (2 * p + h) * 6176 + kk * 772 + j4 * 4) * 4,
                 src);
        }
        cp_commit();
    };

    float acc[4][3][2][4];

    for (int k = 0; k < 10; k++) {
#pragma unroll
        for (int mt = 0; mt < 4; mt++)
#pragma unroll
            for (int g = 0; g < 3; g++)
#pragma unroll
                for (int nt = 0; nt < 2; nt++)
#pragma unroll
                    for (int c = 0; c < 4; c++) acc[mt][g][nt][c] = 0.0f;

        issue(0);
        for (int c = 0; c < 16; c++) {
            if (c + 1 < 16) { issue(c + 1); cp_wait1(); } else { cp_wait0(); }
            __syncthreads();
            const uint32_t* whb = smu + 16896 + 2 * (c & 1) * 6176;
            const uint32_t* wlb = whb + 6176;
#pragma unroll
            for (int pass = 0; pass < 3; pass++) {
                const uint32_t* wb = (pass == 2) ? wlb : whb;
                const uint32_t* hb = (pass == 1) ? hsm_lo : hsm_hi;
                uint32_t bfr[6][2];
#pragma unroll
                for (int g = 0; g < 3; g++)
#pragma unroll
                    for (int nt = 0; nt < 2; nt++) {
                        int n = g * 256 + dbase + 8 * nt + gid;
                        bfr[g * 2 + nt][0] = wb[tidg * 772 + n];
                        bfr[g * 2 + nt][1] = wb[(tidg + 4) * 772 + n];
                    }
#pragma unroll
                for (int mt = 0; mt < 4; mt++) {
                    int row = 16 * mt + gid;
                    int kpc = 8 * c;
                    uint32_t a0 = hb[row * 132 + kpc + tidg];
                    uint32_t a1 = hb[(row + 8) * 132 + kpc + tidg];
                    uint32_t a2 = hb[row * 132 + kpc + 4 + tidg];
                    uint32_t a3 = hb[(row + 8) * 132 + kpc + 4 + tidg];
#pragma unroll
                    for (int g = 0; g < 3; g++)
#pragma unroll
                        for (int nt = 0; nt < 2; nt++)
                            mma16816(acc[mt][g][nt][0], acc[mt][g][nt][1],
                                     acc[mt][g][nt][2], acc[mt][g][nt][3],
                                     a0, a1, a2, a3,
                                     bfr[g * 2 + nt][0], bfr[g * 2 + nt][1]);
                }
            }
            __syncthreads();  // buffer reuse guard; last iter: pre-epilogue guard
        }

        // fused GRU epilogue (each (row,d) cell owned by exactly one thread)
#pragma unroll
        for (int mt = 0; mt < 4; mt++)
#pragma unroll
            for (int rh = 0; rh < 2; rh++) {
                int row = 16 * mt + 8 * rh + gid;
                const float* gi = g_GI + ((size_t)(b * 64 + row) * 10 + k) * 768;
                float yp = 0.0f;
#pragma unroll
                for (int nt = 0; nt < 2; nt++) {
                    int d = dbase + 8 * nt + 2 * tidg;
                    int kp = w * 8 + 4 * nt + tidg;  // = d/2
                    float2 gr = *(const float2*)(gi + d);
                    float2 gz = *(const float2*)(gi + 256 + d);
                    float2 gn = *(const float2*)(gi + 512 + d);
                    uint32_t hh = hsm_hi[row * 132 + kp];
                    uint32_t hl = hsm_lo[row * 132 + kp];
                    float2 hhf = __half22float2(*reinterpret_cast<half2*>(&hh));
                    float2 hlf = __half22float2(*reinterpret_cast<half2*>(&hl));
                    float hox = hhf.x + hlf.x, hoy = hhf.y + hlf.y;
                    int c0 = rh * 2;
                    float r0v = 1.0f / (1.0f + expf(-(gr.x + acc[mt][0][nt][c0])));
                    float r1v = 1.0f / (1.0f + expf(-(gr.y + acc[mt][0][nt][c0 + 1])));
                    float z0v = 1.0f / (1.0f + expf(-(gz.x + acc[mt][1][nt][c0])));
                    float z1v = 1.0f / (1.0f + expf(-(gz.y + acc[mt][1][nt][c0 + 1])));
                    float hn0 = acc[mt][2][nt][c0] + bhn[nt].x;
                    float hn1 = acc[mt][2][nt][c0 + 1] + bhn[nt].y;
                    float n0 = tanhf(gn.x + r0v * hn0);
                    float n1 = tanhf(gn.y + r1v * hn1);
                    float h0n = (1.0f - z0v) * n0 + z0v * hox;
                    float h1n = (1.0f - z1v) * n1 + z1v * hoy;
                    uint32_t nlo, nhi = split_h2(h0n, h1n, nlo);
                    hsm_hi[row * 132 + kp] = nhi;
                    hsm_lo[row * 132 + kp] = nlo;
                    yp += h0n * wo[nt].x + h1n * wo[nt].y;
                }
                yp += __shfl_xor_sync(0xffffffffu, yp, 1);
                yp += __shfl_xor_sync(0xffffffffu, yp, 2);
                if (tidg == 0) atomicAdd(&ysm[row], yp);
            }
        __syncthreads();
        if (tid < 64) {
            out[((size_t)(b * 64) + tid) * 10 + k] = ysm[tid];
            ysm[tid] = bout;
        }
        __syncthreads();  // order out-write/ysm-reset + h writes before next step
    }
}

// ---------------------------------------------------------------------------
extern "C" void kernel_launch(void* const* d_in, const int* in_sizes, int n_in,
                              void* d_out, int out_size) {
    (void)in_sizes; (void)n_in; (void)out_size;
    const float* item_embs = (const float*)d_in[0];  // [128,64,10,256]
    const float* user_embs = (const float*)d_in[1];  // [128,64,256]
    const float* W_ih      = (const float*)d_in[2];  // [768,512]
    const float* W_hh      = (const float*)d_in[3];  // [768,256]
    const float* b_ih      = (const float*)d_in[4];  // [768]
    const float* b_hh      = (const float*)d_in[5];  // [768]
    const float* w_out     = (const float*)d_in[6];  // [256]
    const float* b_out     = (const float*)d_in[7];  // scalar
    const int*   length    = (const int*)d_in[8];    // [128]
    float* out = (float*)d_out;                      // [128,64,10]

    prep_weights<<<384, 256>>>(W_ih, W_hh);
    prep_items<<<10240, 256>>>(item_embs);

    const int gi_smem = 18688 * 4;  // 74752 B
    cudaFuncSetAttribute(gi_tc, cudaFuncAttributeMaxDynamicSharedMemorySize,
                         gi_smem);
    dim3 gg(640, 6);  // 81920/128 x 768/128
    gi_tc<<<gg, 256, gi_smem>>>(b_ih, b_hh);

    const int rnn_smem = 41664 * 4;  // 166656 B
    cudaFuncSetAttribute(rnn_tc, cudaFuncAttributeMaxDynamicSharedMemorySize,
                         rnn_smem);
    rnn_tc<<<128, 512, rnn_smem>>>(user_embs, b_hh, w_out, b_out, length, out);
}

// round 8
// speedup vs baseline: 3.0128x; 1.1489x over previous
#include <cuda_runtime.h>
#include <cuda_fp16.h>
#include <cstdint>
#include <math.h>

// SlatewiseGRU: B=128, S=64, K=10, D=256.
// Input second half is zeros => threshold mask dead, GI GEMM hoisted.
// R6: bank-conflict fixes (B-stage strides 776/136), gi grid swap for A-tile
// L2 reuse, GI L2 prefetch in rnn, fast-math activations.

// ---------------------------------------------------------------------------
static __device__ __forceinline__ uint32_t smem_u32(const void* p) {
    uint32_t a;
    asm("{ .reg .u64 t; cvta.to.shared.u64 t, %1; cvt.u32.u64 %0, t; }"
        : "=r"(a) : "l"(p));
    return a;
}
static __device__ __forceinline__ void cp16(uint32_t dst, const void* src) {
    asm volatile("cp.async.cg.shared.global [%0], [%1], 16;"
                 :: "r"(dst), "l"(src));
}
static __device__ __forceinline__ void cp_commit() {
    asm volatile("cp.async.commit_group;" ::: "memory");
}
static __device__ __forceinline__ void cp_wait1() {
    asm volatile("cp.async.wait_group 1;" ::: "memory");
}
static __device__ __forceinline__ void cp_wait0() {
    asm volatile("cp.async.wait_group 0;" ::: "memory");
}
static __device__ __forceinline__ void prefetch_l2(const void* p) {
    asm volatile("prefetch.global.L2 [%0];" :: "l"(p));
}
// pack two fp32 into f16x2 reg: low half = x0 (even k), high half = x1
static __device__ __forceinline__ uint32_t pack_h2(float x0, float x1) {
    uint32_t r;
    asm("cvt.rn.f16x2.f32 %0, %1, %2;" : "=r"(r) : "f"(x1), "f"(x0));
    return r;
}
// split (x0,x1) into fp16 hi pair + fp16 lo (residual) pair
static __device__ __forceinline__ uint32_t split_h2(float x0, float x1,
                                                    uint32_t& lo) {
    uint32_t hi = pack_h2(x0, x1);
    half2 h = *reinterpret_cast<half2*>(&hi);
    float2 b = __half22float2(h);
    lo = pack_h2(x0 - b.x, x1 - b.y);
    return hi;
}
// D += A(16x16) * B(16x8), fp16 inputs, fp32 accum.
static __device__ __forceinline__ void mma16816(float& d0, float& d1, float& d2,
                                                float& d3, uint32_t a0,
                                                uint32_t a1, uint32_t a2,
                                                uint32_t a3, uint32_t b0,
                                                uint32_t b1) {
    asm("mma.sync.aligned.m16n8k16.row.col.f32.f16.f16.f32 "
        "{%0,%1,%2,%3}, {%4,%5,%6,%7}, {%8,%9}, {%0,%1,%2,%3};"
        : "+f"(d0), "+f"(d1), "+f"(d2), "+f"(d3)
        : "r"(a0), "r"(a1), "r"(a2), "r"(a3), "r"(b0), "r"(b1));
}
static __device__ __forceinline__ float fast_sig(float x) {
    return __fdividef(1.0f, 1.0f + __expf(-x));
}
static __device__ __forceinline__ float fast_tanh(float x) {
    float t = __expf(-2.0f * fabsf(x));
    float r = __fdividef(1.0f - t, 1.0f + t);
    return copysignf(r, x);
}

// Scratch (device globals: allocation-free per harness rules)
__device__ float g_GI[62914560];         // [81920][768] input gates (+biases)
__device__ uint32_t g_IPk_hi[10485760];  // [81920 rows][128 kpair] f16x2 items
__device__ uint32_t g_IPk_lo[10485760];
__device__ uint32_t g_WihPk_hi[98304];   // [128 kpair][768 j] f16x2 W_ih^T
__device__ uint32_t g_WihPk_lo[98304];
__device__ uint32_t g_WhhPk_hi[98304];   // [128 kpair][768 j] f16x2 W_hh^T
__device__ uint32_t g_WhhPk_lo[98304];

// ---------------------------------------------------------------------------
__global__ void prep_weights(const float* __restrict__ W_ih,
                             const float* __restrict__ W_hh) {
    int idx = blockIdx.x * 256 + threadIdx.x;  // 98304 = 128 kpair x 768 j
    if (idx >= 98304) return;
    int kp = idx / 768;
    int j = idx - kp * 768;
    {
        float x0 = W_ih[(size_t)j * 512 + 2 * kp];
        float x1 = W_ih[(size_t)j * 512 + 2 * kp + 1];
        uint32_t lo, hi = split_h2(x0, x1, lo);
        g_WihPk_hi[idx] = hi;
        g_WihPk_lo[idx] = lo;
    }
    {
        float x0 = W_hh[(size_t)j * 256 + 2 * kp];
        float x1 = W_hh[(size_t)j * 256 + 2 * kp + 1];
        uint32_t lo, hi = split_h2(x0, x1, lo);
        g_WhhPk_hi[idx] = hi;
        g_WhhPk_lo[idx] = lo;
    }
}

__global__ void prep_items(const float* __restrict__ A) {
    // 81920 rows x 128 kpairs = 10485760 pairs; 10240 blocks x 256 thr x 4
    int base = blockIdx.x * 256 + threadIdx.x;
#pragma unroll
    for (int it = 0; it < 4; it++) {
        int i = base + it * 2621440;
        float2 v = ((const float2*)A)[i];
        uint32_t lo, hi = split_h2(v.x, v.y, lo);
        g_IPk_hi[i] = hi;
        g_IPk_lo[i] = lo;
    }
}

// ---------------------------------------------------------------------------
// GI[r, j] = sum_k items[r,k] * W_ih[j,k] (+ bias), 3x fp16 split mma.
// Block tile 128x128, 8 warps (2m x 4n), warp tile 64x32.
// K chunked by 32 (16 kpairs), cp.async double-buffered, pre-split operands.
// Grid = (6 j-blocks, 640 r-blocks): j inner => A tiles reused from L2.
__global__ void __launch_bounds__(256, 2) gi_tc(const float* __restrict__ b_ih,
                                                const float* __restrict__ b_hh) {
    extern __shared__ uint32_t smu[];
    // A: (2p+h)*2560 : [128 m][20] (16 kpair + 4 pad)
    // B: 10240 + (2p+h)*2176 : [16 kpair][136] (132+4 pad, stride 136%32==8)
    const uint32_t sbase = smem_u32(smu);
    const int tid = threadIdx.x;
    const int lane = tid & 31, w = tid >> 5;
    const int gid = lane >> 2, tidg = lane & 3;
    const int mbase = (w >> 2) * 64, nbase = (w & 3) * 32;
    const int r0 = blockIdx.y * 128, j0 = blockIdx.x * 128;

    float acc[4][4][4];
#pragma unroll
    for (int mt = 0; mt < 4; mt++)
#pragma unroll
        for (int nt = 0; nt < 4; nt++)
#pragma unroll
            for (int c = 0; c < 4; c++) acc[mt][nt][c] = 0.0f;

    auto issue = [&](int c) {
        int p = c & 1;
        uint32_t aA = sbase + (uint32_t)(2 * p * 2560) * 4;
        uint32_t aB = sbase + (uint32_t)(10240 + 2 * p * 2176) * 4;
#pragma unroll
        for (int it = 0; it < 4; it++) {
            int f = tid + it * 256;           // 1024 cp16: [h][128 m][4 k4]
            int h = f >> 9, rem = f & 511;
            int m = rem >> 2, k4 = rem & 3;
            const uint32_t* src = (h ? g_IPk_lo : g_IPk_hi) +
                                  (size_t)(r0 + m) * 128 + c * 16 + k4 * 4;
            cp16(aA + (uint32_t)(h * 2560 + m * 20 + k4 * 4) * 4, src);
        }
#pragma unroll
        for (int it = 0; it < 4; it++) {
            int f = tid + it * 256;           // 1024 cp16: [h][16 kp][32 j4]
            int h = f >> 9, rem = f & 511;
            int kp = rem >> 5, j4 = rem & 31;
            const uint32_t* src = (h ? g_WihPk_lo : g_WihPk_hi) +
                                  (size_t)(c * 16 + kp) * 768 + j0 + j4 * 4;
            cp16(aB + (uint32_t)(h * 2176 + kp * 136 + j4 * 4) * 4, src);
        }
        cp_commit();
    };

    issue(0);
    for (int c = 0; c < 8; c++) {
        if (c + 1 < 8) { issue(c + 1); cp_wait1(); } else { cp_wait0(); }
        __syncthreads();
        const uint32_t* Ah = smu + 2 * (c & 1) * 2560;
        const uint32_t* Al = Ah + 2560;
        const uint32_t* Bh = smu + 10240 + 2 * (c & 1) * 2176;
        const uint32_t* Bl = Bh + 2176;
#pragma unroll
        for (int ks = 0; ks < 2; ks++) {
            const int kp0 = 8 * ks + tidg, kp1 = kp0 + 4;
            uint32_t bh[4][2], bl[4][2];
#pragma unroll
            for (int nt = 0; nt < 4; nt++) {
                int j = nbase + 8 * nt + gid;
                bh[nt][0] = Bh[kp0 * 136 + j];
                bh[nt][1] = Bh[kp1 * 136 + j];
                bl[nt][0] = Bl[kp0 * 136 + j];
                bl[nt][1] = Bl[kp1 * 136 + j];
            }
#pragma unroll
            for (int mt = 0; mt < 4; mt++) {
                int row = mbase + 16 * mt + gid;
                uint32_t ah0 = Ah[row * 20 + kp0];
                uint32_t ah1 = Ah[(row + 8) * 20 + kp0];
                uint32_t ah2 = Ah[row * 20 + kp1];
                uint32_t ah3 = Ah[(row + 8) * 20 + kp1];
                uint32_t al0 = Al[row * 20 + kp0];
                uint32_t al1 = Al[(row + 8) * 20 + kp0];
                uint32_t al2 = Al[row * 20 + kp1];
                uint32_t al3 = Al[(row + 8) * 20 + kp1];
#pragma unroll
                for (int nt = 0; nt < 4; nt++) {
                    mma16816(acc[mt][nt][0], acc[mt][nt][1], acc[mt][nt][2],
                             acc[mt][nt][3], ah0, ah1, ah2, ah3,
                             bh[nt][0], bh[nt][1]);
                    mma16816(acc[mt][nt][0], acc[mt][nt][1], acc[mt][nt][2],
                             acc[mt][nt][3], al0, al1, al2, al3,
                             bh[nt][0], bh[nt][1]);
                    mma16816(acc[mt][nt][0], acc[mt][nt][1], acc[mt][nt][2],
                             acc[mt][nt][3], ah0, ah1, ah2, ah3,
                             bl[nt][0], bl[nt][1]);
                }
            }
        }
        __syncthreads();  // buffer reuse guard before next issue
    }

    // epilogue: add bias, store float2s
    const bool addh = (j0 + nbase) < 512;
    float2 bias[4];
#pragma unroll
    for (int nt = 0; nt < 4; nt++) {
        int j = j0 + nbase + 8 * nt + 2 * tidg;
        float2 v = *(const float2*)(b_ih + j);
        if (addh) {
            float2 h2 = *(const float2*)(b_hh + j);
            v.x += h2.x; v.y += h2.y;
        }
        bias[nt] = v;
    }
#pragma unroll
    for (int mt = 0; mt < 4; mt++)
#pragma unroll
        for (int rh = 0; rh < 2; rh++) {
            int row = mbase + 16 * mt + 8 * rh + gid;
            float* dst = g_GI + (size_t)(r0 + row) * 768 + j0 + nbase;
#pragma unroll
            for (int nt = 0; nt < 4; nt++) {
                float2 o;
                o.x = acc[mt][nt][2 * rh] + bias[nt].x;
                o.y = acc[mt][nt][2 * rh + 1] + bias[nt].y;
                *(float2*)(dst + 8 * nt + 2 * tidg) = o;
            }
        }
}

// ---------------------------------------------------------------------------
// RNN: one CTA per batch (128 CTAs, 512 threads = 16 warps).
// h kept in SMEM as f16x2 hi/lo pairs (written by epilogue); warp w owns
// d in [16w, 16w+16) across all 3 gates => epilogue fully in-warp.
// Pre-split weights staged per k16-chunk via cp.async (stride 776 =>
// conflict-free), double-buffered. Per-step GI slab prefetched to L2.
__global__ void __launch_bounds__(512) rnn_tc(const float* __restrict__ user_embs,
                                              const float* __restrict__ b_hh,
                                              const float* __restrict__ w_out,
                                              const float* __restrict__ b_out,
                                              const int* __restrict__ length,
                                              float* __restrict__ out) {
    extern __shared__ uint32_t smu[];
    uint32_t* hsm_hi = smu;            // [64][132] (128 kpair + 4 pad)
    uint32_t* hsm_lo = smu + 8448;
    // wbufs @16896 + (2p+h)*6208 : [8 kpair][776]
    float* ysm = (float*)(smu + 41728);  // [64]
    const uint32_t sbase = smem_u32(smu);

    const int b = blockIdx.x;
    const int tid = threadIdx.x;
    const int lane = tid & 31, w = tid >> 5;
    const int gid = lane >> 2, tidg = lane & 3;
    const int dbase = w * 16;

    // h0 = user_embs[b, clip(len-1,0)] broadcast to 64 rows, split to f16 hi/lo
    int hidx = length[b] - 1;
    if (hidx < 0) hidx = 0;
    const float* u0 = user_embs + ((size_t)b * 64 + hidx) * 256;
    for (int i = tid; i < 64 * 128; i += 512) {
        int row = i >> 7, kp = i & 127;
        float2 v = *(const float2*)(u0 + 2 * kp);
        uint32_t lo, hi = split_h2(v.x, v.y, lo);
        hsm_hi[row * 132 + kp] = hi;
        hsm_lo[row * 132 + kp] = lo;
    }
    const float bout = b_out[0];
    if (tid < 64) ysm[tid] = bout;

    float2 bhn[2], wo[2];
#pragma unroll
    for (int nt = 0; nt < 2; nt++) {
        int d = dbase + 8 * nt + 2 * tidg;
        bhn[nt] = *(const float2*)(b_hh + 512 + d);
        wo[nt] = *(const float2*)(w_out + d);
    }

    auto issue = [&](int c) {
        int p = c & 1;
#pragma unroll
        for (int it = 0; it < 6; it++) {
            int f = tid + it * 512;        // 3072 cp16: [h][8 kk][192 j4]
            int h = f / 1536, rem = f - h * 1536;
            int kk = rem / 192, j4 = rem - kk * 192;
            const uint32_t* src = (h ? g_WhhPk_lo : g_WhhPk_hi) +
                                  (size_t)(c * 8 + kk) * 768 + j4 * 4;
            cp16(sbase +
                     (uint32_t)(16896 + (2 * p + h) * 6208 + kk * 776 + j4 * 4) * 4,
                 src);
        }
        cp_commit();
    };

    float acc[4][3][2][4];

    for (int k = 0; k < 10; k++) {
        // prefetch this step's GI slab (64 rows x 768 floats) into L2
        {
            const float* gib = g_GI + ((size_t)(b * 64) * 10 + k) * 768;
            for (int i = tid; i < 1536; i += 512) {
                int r = i / 24, l = i - r * 24;
                prefetch_l2((const char*)(gib + (size_t)r * 7680) + l * 128);
            }
        }
#pragma unroll
        for (int mt = 0; mt < 4; mt++)
#pragma unroll
            for (int g = 0; g < 3; g++)
#pragma unroll
                for (int nt = 0; nt < 2; nt++)
#pragma unroll
                    for (int c = 0; c < 4; c++) acc[mt][g][nt][c] = 0.0f;

        issue(0);
        for (int c = 0; c < 16; c++) {
            if (c + 1 < 16) { issue(c + 1); cp_wait1(); } else { cp_wait0(); }
            __syncthreads();
            const uint32_t* whb = smu + 16896 + 2 * (c & 1) * 6208;
            const uint32_t* wlb = whb + 6208;
#pragma unroll
            for (int pass = 0; pass < 3; pass++) {
                const uint32_t* wb = (pass == 2) ? wlb : whb;
                const uint32_t* hb = (pass == 1) ? hsm_lo : hsm_hi;
                uint32_t bfr[6][2];
#pragma unroll
                for (int g = 0; g < 3; g++)
#pragma unroll
                    for (int nt = 0; nt < 2; nt++) {
                        int n = g * 256 + dbase + 8 * nt + gid;
                        bfr[g * 2 + nt][0] = wb[tidg * 776 + n];
                        bfr[g * 2 + nt][1] = wb[(tidg + 4) * 776 + n];
                    }
#pragma unroll
                for (int mt = 0; mt < 4; mt++) {
                    int row = 16 * mt + gid;
                    int kpc = 8 * c;
                    uint32_t a0 = hb[row * 132 + kpc + tidg];
                    uint32_t a1 = hb[(row + 8) * 132 + kpc + tidg];
                    uint32_t a2 = hb[row * 132 + kpc + 4 + tidg];
                    uint32_t a3 = hb[(row + 8) * 132 + kpc + 4 + tidg];
#pragma unroll
                    for (int g = 0; g < 3; g++)
#pragma unroll
                        for (int nt = 0; nt < 2; nt++)
                            mma16816(acc[mt][g][nt][0], acc[mt][g][nt][1],
                                     acc[mt][g][nt][2], acc[mt][g][nt][3],
                                     a0, a1, a2, a3,
                                     bfr[g * 2 + nt][0], bfr[g * 2 + nt][1]);
                }
            }
            __syncthreads();  // buffer reuse guard; last iter: pre-epilogue guard
        }

        // fused GRU epilogue (each (row,d) cell owned by exactly one thread)
#pragma unroll
        for (int mt = 0; mt < 4; mt++)
#pragma unroll
            for (int rh = 0; rh < 2; rh++) {
                int row = 16 * mt + 8 * rh + gid;
                const float* gi = g_GI + ((size_t)(b * 64 + row) * 10 + k) * 768;
                float yp = 0.0f;
#pragma unroll
                for (int nt = 0; nt < 2; nt++) {
                    int d = dbase + 8 * nt + 2 * tidg;
                    int kp = w * 8 + 4 * nt + tidg;  // = d/2
                    float2 gr = *(const float2*)(gi + d);
                    float2 gz = *(const float2*)(gi + 256 + d);
                    float2 gn = *(const float2*)(gi + 512 + d);
                    uint32_t hh = hsm_hi[row * 132 + kp];
                    uint32_t hl = hsm_lo[row * 132 + kp];
                    float2 hhf = __half22float2(*reinterpret_cast<half2*>(&hh));
                    float2 hlf = __half22float2(*reinterpret_cast<half2*>(&hl));
                    float hox = hhf.x + hlf.x, hoy = hhf.y + hlf.y;
                    int c0 = rh * 2;
                    float r0v = fast_sig(gr.x + acc[mt][0][nt][c0]);
                    float r1v = fast_sig(gr.y + acc[mt][0][nt][c0 + 1]);
                    float z0v = fast_sig(gz.x + acc[mt][1][nt][c0]);
                    float z1v = fast_sig(gz.y + acc[mt][1][nt][c0 + 1]);
                    float hn0 = acc[mt][2][nt][c0] + bhn[nt].x;
                    float hn1 = acc[mt][2][nt][c0 + 1] + bhn[nt].y;
                    float n0 = fast_tanh(gn.x + r0v * hn0);
                    float n1 = fast_tanh(gn.y + r1v * hn1);
                    float h0n = (1.0f - z0v) * n0 + z0v * hox;
                    float h1n = (1.0f - z1v) * n1 + z1v * hoy;
                    uint32_t nlo, nhi = split_h2(h0n, h1n, nlo);
                    hsm_hi[row * 132 + kp] = nhi;
                    hsm_lo[row * 132 + kp] = nlo;
                    yp += h0n * wo[nt].x + h1n * wo[nt].y;
                }
                yp += __shfl_xor_sync(0xffffffffu, yp, 1);
                yp += __shfl_xor_sync(0xffffffffu, yp, 2);
                if (tidg == 0) atomicAdd(&ysm[row], yp);
            }
        __syncthreads();
        if (tid < 64) {
            out[((size_t)(b * 64) + tid) * 10 + k] = ysm[tid];
            ysm[tid] = bout;
        }
        __syncthreads();  // order out-write/ysm-reset + h writes before next step
    }
}

// ---------------------------------------------------------------------------
extern "C" void kernel_launch(void* const* d_in, const int* in_sizes, int n_in,
                              void* d_out, int out_size) {
    (void)in_sizes; (void)n_in; (void)out_size;
    const float* item_embs = (const float*)d_in[0];  // [128,64,10,256]
    const float* user_embs = (const float*)d_in[1];  // [128,64,256]
    const float* W_ih      = (const float*)d_in[2];  // [768,512]
    const float* W_hh      = (const float*)d_in[3];  // [768,256]
    const float* b_ih      = (const float*)d_in[4];  // [768]
    const float* b_hh      = (const float*)d_in[5];  // [768]
    const float* w_out     = (const float*)d_in[6];  // [256]
    const float* b_out     = (const float*)d_in[7];  // scalar
    const int*   length    = (const int*)d_in[8];    // [128]
    float* out = (float*)d_out;                      // [128,64,10]

    prep_weights<<<384, 256>>>(W_ih, W_hh);
    prep_items<<<10240, 256>>>(item_embs);

    const int gi_smem = 18944 * 4;  // 75776 B
    cudaFuncSetAttribute(gi_tc, cudaFuncAttributeMaxDynamicSharedMemorySize,
                         gi_smem);
    dim3 gg(6, 640);  // j-blocks inner => A-tile L2 reuse across 6 j-blocks
    gi_tc<<<gg, 256, gi_smem>>>(b_ih, b_hh);

    const int rnn_smem = 41792 * 4;  // 167168 B
    cudaFuncSetAttribute(rnn_tc, cudaFuncAttributeMaxDynamicSharedMemorySize,
                         rnn_smem);
    rnn_tc<<<128, 512, rnn_smem>>>(user_embs, b_hh, w_out, b_out, length, out);
}

// round 9
// speedup vs baseline: 3.5901x; 1.1916x over previous
#include <cuda_runtime.h>
#include <cuda_fp16.h>
#include <cstdint>
#include <math.h>

// SlatewiseGRU: B=128, S=64, K=10, D=256.
// Input second half is zeros => threshold mask dead, GI GEMM hoisted.
// R8: rnn uses 2-term split (h_hi+h_lo vs fp16 W_hh) => 1/3 fewer mma and
// half the weight staging; chunk size 16 kpairs (8 chunks/step) halves
// barrier count. GI remains 3-term fp16 split (fp32-level accuracy).

// ---------------------------------------------------------------------------
static __device__ __forceinline__ uint32_t smem_u32(const void* p) {
    uint32_t a;
    asm("{ .reg .u64 t; cvta.to.shared.u64 t, %1; cvt.u32.u64 %0, t; }"
        : "=r"(a) : "l"(p));
    return a;
}
static __device__ __forceinline__ void cp16(uint32_t dst, const void* src) {
    asm volatile("cp.async.cg.shared.global [%0], [%1], 16;"
                 :: "r"(dst), "l"(src));
}
static __device__ __forceinline__ void cp_commit() {
    asm volatile("cp.async.commit_group;" ::: "memory");
}
static __device__ __forceinline__ void cp_wait1() {
    asm volatile("cp.async.wait_group 1;" ::: "memory");
}
static __device__ __forceinline__ void cp_wait0() {
    asm volatile("cp.async.wait_group 0;" ::: "memory");
}
static __device__ __forceinline__ void prefetch_l2(const void* p) {
    asm volatile("prefetch.global.L2 [%0];" :: "l"(p));
}
// pack two fp32 into f16x2 reg: low half = x0 (even k), high half = x1
static __device__ __forceinline__ uint32_t pack_h2(float x0, float x1) {
    uint32_t r;
    asm("cvt.rn.f16x2.f32 %0, %1, %2;" : "=r"(r) : "f"(x1), "f"(x0));
    return r;
}
// split (x0,x1) into fp16 hi pair + fp16 lo (residual) pair
static __device__ __forceinline__ uint32_t split_h2(float x0, float x1,
                                                    uint32_t& lo) {
    uint32_t hi = pack_h2(x0, x1);
    half2 h = *reinterpret_cast<half2*>(&hi);
    float2 b = __half22float2(h);
    lo = pack_h2(x0 - b.x, x1 - b.y);
    return hi;
}
// D += A(16x16) * B(16x8), fp16 inputs, fp32 accum.
static __device__ __forceinline__ void mma16816(float& d0, float& d1, float& d2,
                                                float& d3, uint32_t a0,
                                                uint32_t a1, uint32_t a2,
                                                uint32_t a3, uint32_t b0,
                                                uint32_t b1) {
    asm("mma.sync.aligned.m16n8k16.row.col.f32.f16.f16.f32 "
        "{%0,%1,%2,%3}, {%4,%5,%6,%7}, {%8,%9}, {%0,%1,%2,%3};"
        : "+f"(d0), "+f"(d1), "+f"(d2), "+f"(d3)
        : "r"(a0), "r"(a1), "r"(a2), "r"(a3), "r"(b0), "r"(b1));
}
static __device__ __forceinline__ float fast_sig(float x) {
    return __fdividef(1.0f, 1.0f + __expf(-x));
}
static __device__ __forceinline__ float fast_tanh(float x) {
    float t = __expf(-2.0f * fabsf(x));
    float r = __fdividef(1.0f - t, 1.0f + t);
    return copysignf(r, x);
}

// Scratch (device globals: allocation-free per harness rules)
__device__ float g_GI[62914560];         // [81920][768] input gates (+biases)
__device__ uint32_t g_IPk_hi[10485760];  // [81920 rows][128 kpair] f16x2 items
__device__ uint32_t g_IPk_lo[10485760];
__device__ uint32_t g_WihPk_hi[98304];   // [128 kpair][768 j] f16x2 W_ih^T
__device__ uint32_t g_WihPk_lo[98304];
__device__ uint32_t g_WhhPk_hi[98304];   // [128 kpair][768 j] f16x2 W_hh^T

// ---------------------------------------------------------------------------
__global__ void prep_weights(const float* __restrict__ W_ih,
                             const float* __restrict__ W_hh) {
    int idx = blockIdx.x * 256 + threadIdx.x;  // 98304 = 128 kpair x 768 j
    if (idx >= 98304) return;
    int kp = idx / 768;
    int j = idx - kp * 768;
    {
        float x0 = W_ih[(size_t)j * 512 + 2 * kp];
        float x1 = W_ih[(size_t)j * 512 + 2 * kp + 1];
        uint32_t lo, hi = split_h2(x0, x1, lo);
        g_WihPk_hi[idx] = hi;
        g_WihPk_lo[idx] = lo;
    }
    {
        float x0 = W_hh[(size_t)j * 256 + 2 * kp];
        float x1 = W_hh[(size_t)j * 256 + 2 * kp + 1];
        g_WhhPk_hi[idx] = pack_h2(x0, x1);
    }
}

__global__ void prep_items(const float* __restrict__ A) {
    // 81920 rows x 128 kpairs = 10485760 pairs; 10240 blocks x 256 thr x 4
    int base = blockIdx.x * 256 + threadIdx.x;
#pragma unroll
    for (int it = 0; it < 4; it++) {
        int i = base + it * 2621440;
        float2 v = ((const float2*)A)[i];
        uint32_t lo, hi = split_h2(v.x, v.y, lo);
        g_IPk_hi[i] = hi;
        g_IPk_lo[i] = lo;
    }
}

// ---------------------------------------------------------------------------
// GI[r, j] = sum_k items[r,k] * W_ih[j,k] (+ bias), 3x fp16 split mma.
// Block tile 128x128, 8 warps (2m x 4n), warp tile 64x32.
// K chunked by 32 (16 kpairs), cp.async double-buffered, pre-split operands.
// Grid = (6 j-blocks, 640 r-blocks): j inner => A tiles reused from L2.
__global__ void __launch_bounds__(256, 2) gi_tc(const float* __restrict__ b_ih,
                                                const float* __restrict__ b_hh) {
    extern __shared__ uint32_t smu[];
    // A: (2p+h)*2560 : [128 m][20] (16 kpair + 4 pad)
    // B: 10240 + (2p+h)*2176 : [16 kpair][136] (132+4 pad, stride 136%32==8)
    const uint32_t sbase = smem_u32(smu);
    const int tid = threadIdx.x;
    const int lane = tid & 31, w = tid >> 5;
    const int gid = lane >> 2, tidg = lane & 3;
    const int mbase = (w >> 2) * 64, nbase = (w & 3) * 32;
    const int r0 = blockIdx.y * 128, j0 = blockIdx.x * 128;

    float acc[4][4][4];
#pragma unroll
    for (int mt = 0; mt < 4; mt++)
#pragma unroll
        for (int nt = 0; nt < 4; nt++)
#pragma unroll
            for (int c = 0; c < 4; c++) acc[mt][nt][c] = 0.0f;

    auto issue = [&](int c) {
        int p = c & 1;
        uint32_t aA = sbase + (uint32_t)(2 * p * 2560) * 4;
        uint32_t aB = sbase + (uint32_t)(10240 + 2 * p * 2176) * 4;
#pragma unroll
        for (int it = 0; it < 4; it++) {
            int f = tid + it * 256;           // 1024 cp16: [h][128 m][4 k4]
            int h = f >> 9, rem = f & 511;
            int m = rem >> 2, k4 = rem & 3;
            const uint32_t* src = (h ? g_IPk_lo : g_IPk_hi) +
                                  (size_t)(r0 + m) * 128 + c * 16 + k4 * 4;
            cp16(aA + (uint32_t)(h * 2560 + m * 20 + k4 * 4) * 4, src);
        }
#pragma unroll
        for (int it = 0; it < 4; it++) {
            int f = tid + it * 256;           // 1024 cp16: [h][16 kp][32 j4]
            int h = f >> 9, rem = f & 511;
            int kp = rem >> 5, j4 = rem & 31;
            const uint32_t* src = (h ? g_WihPk_lo : g_WihPk_hi) +
                                  (size_t)(c * 16 + kp) * 768 + j0 + j4 * 4;
            cp16(aB + (uint32_t)(h * 2176 + kp * 136 + j4 * 4) * 4, src);
        }
        cp_commit();
    };

    issue(0);
    for (int c = 0; c < 8; c++) {
        if (c + 1 < 8) { issue(c + 1); cp_wait1(); } else { cp_wait0(); }
        __syncthreads();
        const uint32_t* Ah = smu + 2 * (c & 1) * 2560;
        const uint32_t* Al = Ah + 2560;
        const uint32_t* Bh = smu + 10240 + 2 * (c & 1) * 2176;
        const uint32_t* Bl = Bh + 2176;
#pragma unroll
        for (int ks = 0; ks < 2; ks++) {
            const int kp0 = 8 * ks + tidg, kp1 = kp0 + 4;
            uint32_t bh[4][2], bl[4][2];
#pragma unroll
            for (int nt = 0; nt < 4; nt++) {
                int j = nbase + 8 * nt + gid;
                bh[nt][0] = Bh[kp0 * 136 + j];
                bh[nt][1] = Bh[kp1 * 136 + j];
                bl[nt][0] = Bl[kp0 * 136 + j];
                bl[nt][1] = Bl[kp1 * 136 + j];
            }
#pragma unroll
            for (int mt = 0; mt < 4; mt++) {
                int row = mbase + 16 * mt + gid;
                uint32_t ah0 = Ah[row * 20 + kp0];
                uint32_t ah1 = Ah[(row + 8) * 20 + kp0];
                uint32_t ah2 = Ah[row * 20 + kp1];
                uint32_t ah3 = Ah[(row + 8) * 20 + kp1];
                uint32_t al0 = Al[row * 20 + kp0];
                uint32_t al1 = Al[(row + 8) * 20 + kp0];
                uint32_t al2 = Al[row * 20 + kp1];
                uint32_t al3 = Al[(row + 8) * 20 + kp1];
#pragma unroll
                for (int nt = 0; nt < 4; nt++) {
                    mma16816(acc[mt][nt][0], acc[mt][nt][1], acc[mt][nt][2],
                             acc[mt][nt][3], ah0, ah1, ah2, ah3,
                             bh[nt][0], bh[nt][1]);
                    mma16816(acc[mt][nt][0], acc[mt][nt][1], acc[mt][nt][2],
                             acc[mt][nt][3], al0, al1, al2, al3,
                             bh[nt][0], bh[nt][1]);
                    mma16816(acc[mt][nt][0], acc[mt][nt][1], acc[mt][nt][2],
                             acc[mt][nt][3], ah0, ah1, ah2, ah3,
                             bl[nt][0], bl[nt][1]);
                }
            }
        }
        __syncthreads();  // buffer reuse guard before next issue
    }

    // epilogue: add bias, store float2s
    const bool addh = (j0 + nbase) < 512;
    float2 bias[4];
#pragma unroll
    for (int nt = 0; nt < 4; nt++) {
        int j = j0 + nbase + 8 * nt + 2 * tidg;
        float2 v = *(const float2*)(b_ih + j);
        if (addh) {
            float2 h2 = *(const float2*)(b_hh + j);
            v.x += h2.x; v.y += h2.y;
        }
        bias[nt] = v;
    }
#pragma unroll
    for (int mt = 0; mt < 4; mt++)
#pragma unroll
        for (int rh = 0; rh < 2; rh++) {
            int row = mbase + 16 * mt + 8 * rh + gid;
            float* dst = g_GI + (size_t)(r0 + row) * 768 + j0 + nbase;
#pragma unroll
            for (int nt = 0; nt < 4; nt++) {
                float2 o;
                o.x = acc[mt][nt][2 * rh] + bias[nt].x;
                o.y = acc[mt][nt][2 * rh + 1] + bias[nt].y;
                *(float2*)(dst + 8 * nt + 2 * tidg) = o;
            }
        }
}

// ---------------------------------------------------------------------------
// RNN: one CTA per batch (128 CTAs, 512 threads = 16 warps).
// h kept in SMEM as f16x2 hi/lo pairs (written by epilogue); warp w owns
// d in [16w, 16w+16) across all 3 gates => epilogue fully in-warp.
// 2-term split: (h_hi + h_lo) @ fp16(W_hh). Weights (hi only) staged per
// 16-kpair chunk (8 chunks/step) via cp.async, double-buffered; B fragments
// shared across the two h passes.
__global__ void __launch_bounds__(512) rnn_tc(const float* __restrict__ user_embs,
                                              const float* __restrict__ b_hh,
                                              const float* __restrict__ w_out,
                                              const float* __restrict__ b_out,
                                              const int* __restrict__ length,
                                              float* __restrict__ out) {
    extern __shared__ uint32_t smu[];
    uint32_t* hsm_hi = smu;            // [64][132] (128 kpair + 4 pad)
    uint32_t* hsm_lo = smu + 8448;
    // weight bufs @16896 + p*12416 : [16 kp][776]
    float* ysm = (float*)(smu + 41728);  // [64]
    const uint32_t sbase = smem_u32(smu);

    const int b = blockIdx.x;
    const int tid = threadIdx.x;
    const int lane = tid & 31, w = tid >> 5;
    const int gid = lane >> 2, tidg = lane & 3;
    const int dbase = w * 16;

    // h0 = user_embs[b, clip(len-1,0)] broadcast to 64 rows, split to f16 hi/lo
    int hidx = length[b] - 1;
    if (hidx < 0) hidx = 0;
    const float* u0 = user_embs + ((size_t)b * 64 + hidx) * 256;
    for (int i = tid; i < 64 * 128; i += 512) {
        int row = i >> 7, kp = i & 127;
        float2 v = *(const float2*)(u0 + 2 * kp);
        uint32_t lo, hi = split_h2(v.x, v.y, lo);
        hsm_hi[row * 132 + kp] = hi;
        hsm_lo[row * 132 + kp] = lo;
    }
    const float bout = b_out[0];
    if (tid < 64) ysm[tid] = bout;

    float2 bhn[2], wo[2];
#pragma unroll
    for (int nt = 0; nt < 2; nt++) {
        int d = dbase + 8 * nt + 2 * tidg;
        bhn[nt] = *(const float2*)(b_hh + 512 + d);
        wo[nt] = *(const float2*)(w_out + d);
    }

    auto issue = [&](int c) {
        int p = c & 1;
#pragma unroll
        for (int it = 0; it < 6; it++) {
            int f = tid + it * 512;        // 3072 cp16: [16 kk][192 j4]
            int kk = f / 192, j4 = f - kk * 192;
            const uint32_t* src = g_WhhPk_hi + (size_t)(c * 16 + kk) * 768 + j4 * 4;
            cp16(sbase + (uint32_t)(16896 + p * 12416 + kk * 776 + j4 * 4) * 4,
                 src);
        }
        cp_commit();
    };

    float acc[4][3][2][4];

    for (int k = 0; k < 10; k++) {
        // prefetch this step's GI slab (64 rows x 768 floats) into L2
        {
            const float* gib = g_GI + ((size_t)(b * 64) * 10 + k) * 768;
            for (int i = tid; i < 1536; i += 512) {
                int r = i / 24, l = i - r * 24;
                prefetch_l2((const char*)(gib + (size_t)r * 7680) + l * 128);
            }
        }
#pragma unroll
        for (int mt = 0; mt < 4; mt++)
#pragma unroll
            for (int g = 0; g < 3; g++)
#pragma unroll
                for (int nt = 0; nt < 2; nt++)
#pragma unroll
                    for (int c = 0; c < 4; c++) acc[mt][g][nt][c] = 0.0f;

        issue(0);
        for (int c = 0; c < 8; c++) {
            if (c + 1 < 8) { issue(c + 1); cp_wait1(); } else { cp_wait0(); }
            __syncthreads();
            const uint32_t* wb = smu + 16896 + (c & 1) * 12416;
#pragma unroll
            for (int ks = 0; ks < 2; ks++) {
                // B fragments (w_hi), shared by both h passes
                uint32_t bfr[6][2];
#pragma unroll
                for (int g = 0; g < 3; g++)
#pragma unroll
                    for (int nt = 0; nt < 2; nt++) {
                        int n = g * 256 + dbase + 8 * nt + gid;
                        bfr[g * 2 + nt][0] = wb[(8 * ks + tidg) * 776 + n];
                        bfr[g * 2 + nt][1] = wb[(8 * ks + tidg + 4) * 776 + n];
                    }
                const int kpc = 16 * c + 8 * ks;
#pragma unroll
                for (int pass = 0; pass < 2; pass++) {
                    const uint32_t* hb = pass ? hsm_lo : hsm_hi;
#pragma unroll
                    for (int mt = 0; mt < 4; mt++) {
                        int row = 16 * mt + gid;
                        uint32_t a0 = hb[row * 132 + kpc + tidg];
                        uint32_t a1 = hb[(row + 8) * 132 + kpc + tidg];
                        uint32_t a2 = hb[row * 132 + kpc + 4 + tidg];
                        uint32_t a3 = hb[(row + 8) * 132 + kpc + 4 + tidg];
#pragma unroll
                        for (int g = 0; g < 3; g++)
#pragma unroll
                            for (int nt = 0; nt < 2; nt++)
                                mma16816(acc[mt][g][nt][0], acc[mt][g][nt][1],
                                         acc[mt][g][nt][2], acc[mt][g][nt][3],
                                         a0, a1, a2, a3,
                                         bfr[g * 2 + nt][0], bfr[g * 2 + nt][1]);
                    }
                }
            }
            __syncthreads();  // buffer reuse guard; last iter: pre-epilogue guard
        }

        // fused GRU epilogue (each (row,d) cell owned by exactly one thread)
#pragma unroll
        for (int mt = 0; mt < 4; mt++)
#pragma unroll
            for (int rh = 0; rh < 2; rh++) {
                int row = 16 * mt + 8 * rh + gid;
                const float* gi = g_GI + ((size_t)(b * 64 + row) * 10 + k) * 768;
                float yp = 0.0f;
#pragma unroll
                for (int nt = 0; nt < 2; nt++) {
                    int d = dbase + 8 * nt + 2 * tidg;
                    int kp = w * 8 + 4 * nt + tidg;  // = d/2
                    float2 gr = *(const float2*)(gi + d);
                    float2 gz = *(const float2*)(gi + 256 + d);
                    float2 gn = *(const float2*)(gi + 512 + d);
                    uint32_t hh = hsm_hi[row * 132 + kp];
                    uint32_t hl = hsm_lo[row * 132 + kp];
                    float2 hhf = __half22float2(*reinterpret_cast<half2*>(&hh));
                    float2 hlf = __half22float2(*reinterpret_cast<half2*>(&hl));
                    float hox = hhf.x + hlf.x, hoy = hhf.y + hlf.y;
                    int c0 = rh * 2;
                    float r0v = fast_sig(gr.x + acc[mt][0][nt][c0]);
                    float r1v = fast_sig(gr.y + acc[mt][0][nt][c0 + 1]);
                    float z0v = fast_sig(gz.x + acc[mt][1][nt][c0]);
                    float z1v = fast_sig(gz.y + acc[mt][1][nt][c0 + 1]);
                    float hn0 = acc[mt][2][nt][c0] + bhn[nt].x;
                    float hn1 = acc[mt][2][nt][c0 + 1] + bhn[nt].y;
                    float n0 = fast_tanh(gn.x + r0v * hn0);
                    float n1 = fast_tanh(gn.y + r1v * hn1);
                    float h0n = (1.0f - z0v) * n0 + z0v * hox;
                    float h1n = (1.0f - z1v) * n1 + z1v * hoy;
                    uint32_t nlo, nhi = split_h2(h0n, h1n, nlo);
                    hsm_hi[row * 132 + kp] = nhi;
                    hsm_lo[row * 132 + kp] = nlo;
                    yp += h0n * wo[nt].x + h1n * wo[nt].y;
                }
                yp += __shfl_xor_sync(0xffffffffu, yp, 1);
                yp += __shfl_xor_sync(0xffffffffu, yp, 2);
                if (tidg == 0) atomicAdd(&ysm[row], yp);
            }
        __syncthreads();
        if (tid < 64) {
            out[((size_t)(b * 64) + tid) * 10 + k] = ysm[tid];
            ysm[tid] = bout;
        }
        __syncthreads();  // order out-write/ysm-reset + h writes before next step
    }
}

// ---------------------------------------------------------------------------
extern "C" void kernel_launch(void* const* d_in, const int* in_sizes, int n_in,
                              void* d_out, int out_size) {
    (void)in_sizes; (void)n_in; (void)out_size;
    const float* item_embs = (const float*)d_in[0];  // [128,64,10,256]
    const float* user_embs = (const float*)d_in[1];  // [128,64,256]
    const float* W_ih      = (const float*)d_in[2];  // [768,512]
    const float* W_hh      = (const float*)d_in[3];  // [768,256]
    const float* b_ih      = (const float*)d_in[4];  // [768]
    const float* b_hh      = (const float*)d_in[5];  // [768]
    const float* w_out     = (const float*)d_in[6];  // [256]
    const float* b_out     = (const float*)d_in[7];  // scalar
    const int*   length    = (const int*)d_in[8];    // [128]
    float* out = (float*)d_out;                      // [128,64,10]

    prep_weights<<<384, 256>>>(W_ih, W_hh);
    prep_items<<<10240, 256>>>(item_embs);

    const int gi_smem = 18944 * 4;  // 75776 B
    cudaFuncSetAttribute(gi_tc, cudaFuncAttributeMaxDynamicSharedMemorySize,
                         gi_smem);
    dim3 gg(6, 640);  // j-blocks inner => A-tile L2 reuse across 6 j-blocks
    gi_tc<<<gg, 256, gi_smem>>>(b_ih, b_hh);

    const int rnn_smem = 41792 * 4;  // 167168 B
    cudaFuncSetAttribute(rnn_tc, cudaFuncAttributeMaxDynamicSharedMemorySize,
                         rnn_smem);
    rnn_tc<<<128, 512, rnn_smem>>>(user_embs, b_hh, w_out, b_out, length, out);
}